// round 13
// baseline (speedup 1.0000x reference)
#include <cuda_runtime.h>
#include <cuda_bf16.h>
#include <math_constants.h>
#include <cstdint>

// Problem constants
#define NPTS   32768
#define DIM    256
#define NCODE  8192
#define HWSZ   1024
#define ZQ_ELEMS (32*256*32*32)

// Tiling
#define BM 64                  // points per CTA
#define NT 64                  // codes per tile
#define NTILES (NCODE/NT)      // 128
#define MARGIN 1.5f
#define NSLOT 32               // candidate slots per point

// SMEM layout (bytes)
#define SM_EB    0                 // e tile double-buffered 2 x 32768
#define SM_EN    65536             // 2 x 64 floats (512)
#define SM_PBD   66048             // 64 uints: encoded per-point running approx min
#define SM_PCNT  66304             // 64 ints: per-point candidate count
#define SM_PCD   66560             // 64 x 32 floats (8192)
#define SM_PCK   74752             // 64 x 32 ints (8192)
#define SMEM_TOTAL 82944

__device__ float g_enorm[NCODE];
__device__ int   g_best_idx[NPTS];
__device__ unsigned int g_flag[NPTS];
__device__ __align__(16) __nv_bfloat16 g_zhi[NPTS * DIM];
__device__ __align__(16) __nv_bfloat16 g_ehi[NCODE * DIM];

// ---------------- PTX helpers (baseline ISA only) ----------------
__device__ __forceinline__ uint32_t smem_u32(const void* p) {
    uint32_t a;
    asm("{ .reg .u64 t; cvta.to.shared.u64 t, %1; cvt.u32.u64 %0, t; }"
        : "=r"(a) : "l"(p));
    return a;
}

__device__ __forceinline__ void cp_async16(uint32_t dst, const void* src) {
    asm volatile("cp.async.cg.shared.global [%0], [%1], 16;"
        :: "r"(dst), "l"(src) : "memory");
}
#define CP_COMMIT() asm volatile("cp.async.commit_group;" ::: "memory")
#define CP_WAIT0()  asm volatile("cp.async.wait_group 0;" ::: "memory")

__device__ __forceinline__ void mma_bf16(float* c, uint32_t a0, uint32_t a1,
                                         uint32_t a2, uint32_t a3,
                                         uint32_t b0, uint32_t b1) {
    asm volatile(
        "mma.sync.aligned.m16n8k16.row.col.f32.bf16.bf16.f32 "
        "{%0,%1,%2,%3}, {%4,%5,%6,%7}, {%8,%9}, {%0,%1,%2,%3};"
        : "+f"(c[0]), "+f"(c[1]), "+f"(c[2]), "+f"(c[3])
        : "r"(a0), "r"(a1), "r"(a2), "r"(a3), "r"(b0), "r"(b1));
}

__device__ __forceinline__ void ldsm_x4(uint32_t* r, uint32_t addr) {
    asm volatile("ldmatrix.sync.aligned.m8n8.x4.shared.b16 {%0,%1,%2,%3}, [%4];"
        : "=r"(r[0]), "=r"(r[1]), "=r"(r[2]), "=r"(r[3]) : "r"(addr));
}

// ---- monotonic float<->uint encoding: enc(a) < enc(b) iff a < b ----
__device__ __forceinline__ uint32_t fenc(float f) {
    uint32_t u = __float_as_uint(f);
    return (u & 0x80000000u) ? ~u : (u | 0x80000000u);
}
__device__ __forceinline__ float fdec(uint32_t u) {
    u = (u & 0x80000000u) ? (u ^ 0x80000000u) : ~u;
    return __uint_as_float(u);
}

// ---------------- Kernel 0: codebook row norms ----------------
__global__ void k_enorm(const float* __restrict__ emb) {
    int warp = (blockIdx.x * blockDim.x + threadIdx.x) >> 5;
    int lane = threadIdx.x & 31;
    if (warp >= NCODE) return;
    const float4* r = reinterpret_cast<const float4*>(emb + (size_t)warp * DIM);
    float4 a = r[lane];
    float4 b = r[lane + 32];
    float s = a.x*a.x + a.y*a.y + a.z*a.z + a.w*a.w
            + b.x*b.x + b.y*b.y + b.z*b.z + b.w*b.w;
    #pragma unroll
    for (int off = 16; off > 0; off >>= 1)
        s += __shfl_xor_sync(0xffffffffu, s, off);
    if (lane == 0) g_enorm[warp] = s;
}

// ---------------- Kernel 0b: e -> bf16 ----------------
__global__ void k_esplit(const float* __restrict__ emb) {
    int i = blockIdx.x * 256 + threadIdx.x;
    if (i >= NCODE * DIM) return;
    g_ehi[i] = __float2bfloat16(emb[i]);
}

// ---------------- Kernel 0c: transpose z -> bf16 (n-major) ----------------
__global__ void k_zsplit(const float* __restrict__ z) {
    __shared__ float s[64][65];
    int bid = blockIdx.x;
    int b   = bid >> 6;
    int hwb = (bid >> 2) & 15;
    int cb  = bid & 3;
    int hw0 = hwb * 64, c0 = cb * 64;
    const float* zb = z + (size_t)b * DIM * HWSZ;
    int t = threadIdx.x;
    #pragma unroll
    for (int i = t; i < 4096; i += 256) {
        int c = i >> 6, hw = i & 63;
        s[hw][c] = zb[(size_t)(c0 + c) * HWSZ + hw0 + hw];
    }
    __syncthreads();
    int n0 = b * HWSZ + hw0;
    #pragma unroll
    for (int i = t; i < 4096; i += 256) {
        int hw = i >> 6, c = i & 63;
        g_zhi[(size_t)(n0 + hw) * DIM + c0 + c] = __float2bfloat16(s[hw][c]);
    }
}

// ---------------- Kernel 1: bf16 HMMA GEMM + true-min shared bound + exact rescore ----------------
__global__ void __launch_bounds__(256, 2)
k_vq(const float* __restrict__ z, const float* __restrict__ emb) {
    extern __shared__ char smem[];
    const uint32_t sb = smem_u32(smem);
    const int tid   = threadIdx.x;
    const int w     = tid >> 5;
    const int lane  = tid & 31;
    const int mgrp  = w >> 1;          // 0..3: which 16 point-rows
    const int ngrp  = w & 1;           // 0..1: which 32-code half of the tile
    const int q     = lane >> 2;
    const int e     = lane & 3;
    const int n0    = blockIdx.x * BM;

    float*    en_s  = reinterpret_cast<float*>(smem + SM_EN);
    uint32_t* pbd_u = reinterpret_cast<uint32_t*>(smem + SM_PBD);
    int*      pcnt_s= reinterpret_cast<int*>(smem + SM_PCNT);
    float*    pcd_s = reinterpret_cast<float*>(smem + SM_PCD);
    int*      pck_s = reinterpret_cast<int*>(smem + SM_PCK);

    if (tid < BM) { pbd_u[tid] = 0xFFFFFFFFu; pcnt_s[tid] = 0; }

    // ---- Resident A fragments: 16 rows x full K=256, bf16 (64 regs) ----
    uint32_t Ah[64];
    {
        const __nv_bfloat16* zh1 = g_zhi + (size_t)(n0 + mgrp * 16 + q) * DIM;
        const __nv_bfloat16* zh2 = zh1 + 8 * DIM;
        #pragma unroll
        for (int ks = 0; ks < 16; ++ks) {
            int c0 = ks * 16 + 2 * e;
            Ah[ks*4+0] = *reinterpret_cast<const uint32_t*>(zh1 + c0);
            Ah[ks*4+1] = *reinterpret_cast<const uint32_t*>(zh2 + c0);
            Ah[ks*4+2] = *reinterpret_cast<const uint32_t*>(zh1 + c0 + 8);
            Ah[ks*4+3] = *reinterpret_cast<const uint32_t*>(zh2 + c0 + 8);
        }
    }

    // ---- B ldmatrix lane constants ----
    const int nl  = (lane & 7) | ((lane >> 4) << 3);
    const int h   = (lane >> 3) & 1;
    const int nl7 = nl & 7;

    // ---- cp.async prefetch: 256 thr x 8 x 16B = 32KB tile ----
    const int prow = tid >> 2;        // 0..63 (code row)
    const int pseg = tid & 3;         // 16B seg pair: pseg and pseg+4
    const uint32_t psw0 = (uint32_t)(((pseg    ) ^ (prow & 7)) << 4);
    const uint32_t psw1 = (uint32_t)(((pseg + 4) ^ (prow & 7)) << 4);
    auto prefetch = [&](int t, int buf) {
        const __nv_bfloat16* gh = g_ehi + (size_t)(t * NT + prow) * DIM;
        uint32_t dbase = sb + SM_EB + buf * 32768 + prow * 128;
        #pragma unroll
        for (int dcp = 0; dcp < 4; ++dcp) {
            cp_async16(dbase + dcp * 8192 + psw0, gh + dcp * 64 + pseg * 8);
            cp_async16(dbase + dcp * 8192 + psw1, gh + dcp * 64 + pseg * 8 + 32);
        }
        CP_COMMIT();
    };

    const int p0 = mgrp * 16 + q;
    const int p1 = p0 + 8;

    prefetch(0, 0);
    if (tid < NT) en_s[tid] = g_enorm[tid];

    #pragma unroll 1
    for (int t1 = 0; t1 < NTILES; ++t1) {
        CP_WAIT0();          // tile t1 data arrived (this thread's portion)
        __syncthreads();     // (a) tile t1 visible to all; (b) ALL warps finished
                             //     iteration t1-1, so buffer (t1+1)&1 is free to
                             //     overwrite (the R12 race fix: prefetch AFTER this)
        if (t1 + 1 < NTILES) {
            prefetch(t1 + 1, (t1 + 1) & 1);
            if (tid < NT)
                en_s[((t1 + 1) & 1) * NT + tid] = g_enorm[(t1 + 1) * NT + tid];
        }

        float acc[16];
        #pragma unroll
        for (int i = 0; i < 16; ++i) acc[i] = 0.f;

        const uint32_t ebase = sb + SM_EB + (t1 & 1) * 32768 + (ngrp * 32 + nl) * 128;
        // B address for k-step ks
        auto baddr = [&](int ks) -> uint32_t {
            return ebase + (ks >> 2) * 8192
                 + (uint32_t)(((((ks & 3) * 2) + h) ^ nl7) << 4);
        };

        // 3-buffer rotation, prefetch distance 2, fully unrolled (no reg copies)
        uint32_t B[3][8];
        { uint32_t pa = baddr(0); ldsm_x4(B[0], pa); ldsm_x4(B[0] + 4, pa + 2048); }
        { uint32_t pa = baddr(1); ldsm_x4(B[1], pa); ldsm_x4(B[1] + 4, pa + 2048); }
        #pragma unroll
        for (int ks = 0; ks < 16; ++ks) {
            if (ks + 2 < 16) {
                uint32_t pa = baddr(ks + 2);
                ldsm_x4(B[(ks + 2) % 3], pa);
                ldsm_x4(B[(ks + 2) % 3] + 4, pa + 2048);
            }
            const uint32_t* Bk = B[ks % 3];
            uint32_t a0 = Ah[ks*4+0], a1 = Ah[ks*4+1],
                     a2 = Ah[ks*4+2], a3 = Ah[ks*4+3];
            mma_bf16(acc + 0,  a0, a1, a2, a3, Bk[0], Bk[1]);
            mma_bf16(acc + 4,  a0, a1, a2, a3, Bk[2], Bk[3]);
            mma_bf16(acc + 8,  a0, a1, a2, a3, Bk[4], Bk[5]);
            mma_bf16(acc + 12, a0, a1, a2, a3, Bk[6], Bk[7]);
        }

        // ---- convert acc -> approx distances (in place) ----
        const float* enb = en_s + (t1 & 1) * NT;
        #pragma unroll
        for (int jj = 0; jj < 2; ++jj) {
            #pragma unroll
            for (int cp = 0; cp < 2; ++cp) {
                int cl = ngrp * 32 + jj * 16 + cp * 8 + 2 * e;
                float2 en2 = *reinterpret_cast<const float2*>(enb + cl);
                float* a = acc + jj * 8 + cp * 4;
                a[0] = fmaf(-2.0f, a[0], en2.x);
                a[1] = fmaf(-2.0f, a[1], en2.y);
                a[2] = fmaf(-2.0f, a[2], en2.x);
                a[3] = fmaf(-2.0f, a[3], en2.y);
            }
        }
        // slot mins (8 values each)
        float m0 = fminf(fminf(fminf(acc[0], acc[1]), fminf(acc[4], acc[5])),
                         fminf(fminf(acc[8], acc[9]), fminf(acc[12], acc[13])));
        float m1 = fminf(fminf(fminf(acc[2], acc[3]), fminf(acc[6], acc[7])),
                         fminf(fminf(acc[10], acc[11]), fminf(acc[14], acc[15])));
        uint32_t e0 = fenc(m0), e1 = fenc(m1);

        if (t1 == 0) {   // seed TRUE min of tile 0 before any recording
            atomicMin(&pbd_u[p0], e0);
            atomicMin(&pbd_u[p1], e1);
            __syncthreads();
        }

        float b0 = fdec(pbd_u[p0]) + MARGIN;   // true running min
        float b1 = fdec(pbd_u[p1]) + MARGIN;
        if (m0 < b0 || m1 < b1) {   // rare
            #pragma unroll
            for (int jj = 0; jj < 2; ++jj) {
                #pragma unroll
                for (int cp = 0; cp < 2; ++cp) {
                    int k0 = t1 * NT + ngrp * 32 + jj * 16 + cp * 8 + 2 * e;
                    const float* a = acc + jj * 8 + cp * 4;
                    if (a[0] < b0) {
                        int s = atomicAdd(&pcnt_s[p0], 1);
                        if (s < NSLOT) { pcd_s[p0*NSLOT+s] = a[0]; pck_s[p0*NSLOT+s] = k0; }
                    }
                    if (a[1] < b0) {
                        int s = atomicAdd(&pcnt_s[p0], 1);
                        if (s < NSLOT) { pcd_s[p0*NSLOT+s] = a[1]; pck_s[p0*NSLOT+s] = k0+1; }
                    }
                    if (a[2] < b1) {
                        int s = atomicAdd(&pcnt_s[p1], 1);
                        if (s < NSLOT) { pcd_s[p1*NSLOT+s] = a[2]; pck_s[p1*NSLOT+s] = k0; }
                    }
                    if (a[3] < b1) {
                        int s = atomicAdd(&pcnt_s[p1], 1);
                        if (s < NSLOT) { pcd_s[p1*NSLOT+s] = a[3]; pck_s[p1*NSLOT+s] = k0+1; }
                    }
                }
            }
        }
        if (t1 > 0) {
            if (e0 < pbd_u[p0]) atomicMin(&pbd_u[p0], e0);
            if (e1 < pbd_u[p1]) atomicMin(&pbd_u[p1], e1);
        }
    }

    // ---- exact fp32 rescore of recorded candidates ----
    __syncthreads();
    if (tid < BM) {
        int p = tid;
        int n = n0 + p;
        int cnt = pcnt_s[p];
        int ov = (cnt > NSLOT);
        int lim = ov ? NSLOT : cnt;
        float bound = fdec(pbd_u[p]) + MARGIN;
        const float* zr = z + (size_t)(n >> 10) * (DIM * HWSZ) + (n & 1023);
        float bestd = CUDART_INF_F; int bestk = 0x7fffffff;
        #pragma unroll 1
        for (int j = 0; j < lim; ++j) {
            float dv = pcd_s[p * NSLOT + j];
            if (!(dv < bound)) continue;
            int kv = pck_s[p * NSLOT + j];
            const float* er = emb + (size_t)kv * DIM;
            float dot = 0.f;
            #pragma unroll 8
            for (int c = 0; c < DIM; ++c)
                dot = fmaf(zr[(size_t)c * HWSZ], er[c], dot);
            float dd = fmaf(-2.0f, dot, g_enorm[kv]);
            if (dd < bestd || (dd == bestd && kv < bestk)) { bestd = dd; bestk = kv; }
        }
        g_best_idx[n] = bestk;
        g_flag[n] = (unsigned)ov;
    }
}

// ---------------- Kernel 1b: exact full-scan fallback for overflowed points ----------------
__global__ void k_fb(const float* __restrict__ z, const float* __restrict__ emb) {
    int w = (blockIdx.x * blockDim.x + threadIdx.x) >> 5;
    int lane = threadIdx.x & 31;
    if (w >= NPTS) return;
    if (g_flag[w] == 0) return;
    const float* zr = z + (size_t)(w >> 10) * (DIM * HWSZ) + (w & 1023);
    float bd = CUDART_INF_F; int bk = 0x7fffffff;
    for (int k = lane; k < NCODE; k += 32) {
        const float* er = emb + (size_t)k * DIM;
        float dot = 0.f;
        #pragma unroll 8
        for (int c = 0; c < DIM; ++c)
            dot = fmaf(zr[(size_t)c * HWSZ], er[c], dot);
        float dd = fmaf(-2.0f, dot, g_enorm[k]);
        if (dd < bd || (dd == bd && k < bk)) { bd = dd; bk = k; }
    }
    #pragma unroll
    for (int off = 16; off > 0; off >>= 1) {
        float od = __shfl_xor_sync(0xffffffffu, bd, off);
        int   ok = __shfl_xor_sync(0xffffffffu, bk, off);
        if (od < bd || (od == bd && ok < bk)) { bd = od; bk = ok; }
    }
    if (lane == 0) g_best_idx[w] = bk;
}

// ---------------- Kernel 2: output writer ----------------
__global__ void k_write(const float* __restrict__ z, const float* __restrict__ emb,
                        float* __restrict__ out, int out_size) {
    int i = blockIdx.x * 256 + threadIdx.x;
    if (i >= out_size) return;
    if (i < ZQ_ELEMS) {
        int hw = i & 1023;
        int bc = i >> 10;
        int c  = bc & 255;
        int b  = bc >> 8;
        int n  = (b << 10) + hw;
        int k  = g_best_idx[n];
        float ev = emb[(size_t)k * DIM + c];
        float zv = z[i];
        out[i] = __fadd_rn(zv, __fsub_rn(ev, zv));
    } else {
        int j = i - ZQ_ELEMS;
        out[i] = (j < NPTS) ? (float)g_best_idx[j] : 0.0f;
    }
}

extern "C" void kernel_launch(void* const* d_in, const int* in_sizes, int n_in,
                              void* d_out, int out_size) {
    const float* z   = (const float*)d_in[0];
    const float* emb = (const float*)d_in[1];
    if (in_sizes[0] != ZQ_ELEMS) {
        const float* tmp = z; z = emb; emb = tmp;
    }
    float* out = (float*)d_out;

    cudaFuncSetAttribute(k_vq, cudaFuncAttributeMaxDynamicSharedMemorySize,
                         SMEM_TOTAL);

    k_enorm<<<NCODE / 8, 256>>>(emb);
    k_esplit<<<(NCODE * DIM) / 256, 256>>>(emb);
    k_zsplit<<<2048, 256>>>(z);
    k_vq<<<NPTS / BM, 256, SMEM_TOTAL>>>(z, emb);
    k_fb<<<NPTS / 8, 256>>>(z, emb);
    int wgrid = (out_size + 255) / 256;
    k_write<<<wgrid, 256>>>(z, emb, out, out_size);
}

// round 14
// speedup vs baseline: 1.0624x; 1.0624x over previous
#include <cuda_runtime.h>
#include <cuda_bf16.h>
#include <math_constants.h>
#include <cstdint>

// Problem constants
#define NPTS   32768
#define DIM    256
#define NCODE  8192
#define HWSZ   1024
#define ZQ_ELEMS (32*256*32*32)

// Tiling
#define BM 128                 // points per CTA
#define NT 64                  // codes per tile
#define NTILES (NCODE/NT)      // 128
#define MARGIN 1.5f
#define NSLOT 32               // candidate slots per point

// SMEM layout (bytes)
#define SM_EB    0                 // e tile 4-buffered: 4 x 32768 = 131072
#define SM_EN    131072            // 4 x 64 floats (1024)
#define SM_PBD   132096            // 128 uints (512)
#define SM_PCNT  132608            // 128 ints (512)
#define SM_PCD   133120            // 128 x 32 floats (16384)
#define SM_PCK   149504            // 128 x 32 ints (16384)
#define SMEM_TOTAL 165888

__device__ float g_enorm[NCODE];
__device__ int   g_best_idx[NPTS];
__device__ unsigned int g_flag[NPTS];
__device__ __align__(16) __nv_bfloat16 g_zhi[NPTS * DIM];
__device__ __align__(16) __nv_bfloat16 g_ehi[NCODE * DIM];

// ---------------- PTX helpers (baseline ISA only) ----------------
__device__ __forceinline__ uint32_t smem_u32(const void* p) {
    uint32_t a;
    asm("{ .reg .u64 t; cvta.to.shared.u64 t, %1; cvt.u32.u64 %0, t; }"
        : "=r"(a) : "l"(p));
    return a;
}

__device__ __forceinline__ void cp_async16(uint32_t dst, const void* src) {
    asm volatile("cp.async.cg.shared.global [%0], [%1], 16;"
        :: "r"(dst), "l"(src) : "memory");
}
#define CP_COMMIT() asm volatile("cp.async.commit_group;" ::: "memory")
#define CP_WAIT0()  asm volatile("cp.async.wait_group 0;" ::: "memory")

__device__ __forceinline__ void mma_bf16(float* c, uint32_t a0, uint32_t a1,
                                         uint32_t a2, uint32_t a3,
                                         uint32_t b0, uint32_t b1) {
    asm volatile(
        "mma.sync.aligned.m16n8k16.row.col.f32.bf16.bf16.f32 "
        "{%0,%1,%2,%3}, {%4,%5,%6,%7}, {%8,%9}, {%0,%1,%2,%3};"
        : "+f"(c[0]), "+f"(c[1]), "+f"(c[2]), "+f"(c[3])
        : "r"(a0), "r"(a1), "r"(a2), "r"(a3), "r"(b0), "r"(b1));
}

__device__ __forceinline__ void ldsm_x4(uint32_t* r, uint32_t addr) {
    asm volatile("ldmatrix.sync.aligned.m8n8.x4.shared.b16 {%0,%1,%2,%3}, [%4];"
        : "=r"(r[0]), "=r"(r[1]), "=r"(r[2]), "=r"(r[3]) : "r"(addr));
}

// ---- monotonic float<->uint encoding: enc(a) < enc(b) iff a < b ----
__device__ __forceinline__ uint32_t fenc(float f) {
    uint32_t u = __float_as_uint(f);
    return (u & 0x80000000u) ? ~u : (u | 0x80000000u);
}
__device__ __forceinline__ float fdec(uint32_t u) {
    u = (u & 0x80000000u) ? (u ^ 0x80000000u) : ~u;
    return __uint_as_float(u);
}

// ---------------- Kernel 0: codebook row norms ----------------
__global__ void k_enorm(const float* __restrict__ emb) {
    int warp = (blockIdx.x * blockDim.x + threadIdx.x) >> 5;
    int lane = threadIdx.x & 31;
    if (warp >= NCODE) return;
    const float4* r = reinterpret_cast<const float4*>(emb + (size_t)warp * DIM);
    float4 a = r[lane];
    float4 b = r[lane + 32];
    float s = a.x*a.x + a.y*a.y + a.z*a.z + a.w*a.w
            + b.x*b.x + b.y*b.y + b.z*b.z + b.w*b.w;
    #pragma unroll
    for (int off = 16; off > 0; off >>= 1)
        s += __shfl_xor_sync(0xffffffffu, s, off);
    if (lane == 0) g_enorm[warp] = s;
}

// ---------------- Kernel 0b: e -> bf16 ----------------
__global__ void k_esplit(const float* __restrict__ emb) {
    int i = blockIdx.x * 256 + threadIdx.x;
    if (i >= NCODE * DIM) return;
    g_ehi[i] = __float2bfloat16(emb[i]);
}

// ---------------- Kernel 0c: transpose z -> bf16 (n-major) ----------------
__global__ void k_zsplit(const float* __restrict__ z) {
    __shared__ float s[64][65];
    int bid = blockIdx.x;
    int b   = bid >> 6;
    int hwb = (bid >> 2) & 15;
    int cb  = bid & 3;
    int hw0 = hwb * 64, c0 = cb * 64;
    const float* zb = z + (size_t)b * DIM * HWSZ;
    int t = threadIdx.x;
    #pragma unroll
    for (int i = t; i < 4096; i += 256) {
        int c = i >> 6, hw = i & 63;
        s[hw][c] = zb[(size_t)(c0 + c) * HWSZ + hw0 + hw];
    }
    __syncthreads();
    int n0 = b * HWSZ + hw0;
    #pragma unroll
    for (int i = t; i < 4096; i += 256) {
        int hw = i >> 6, c = i & 63;
        g_zhi[(size_t)(n0 + hw) * DIM + c0 + c] = __float2bfloat16(s[hw][c]);
    }
}

// ---------------- Kernel 1: bf16 HMMA GEMM, 4-stage pipeline, barrier per 2 tiles ----
__global__ void __launch_bounds__(512, 1)
k_vq(const float* __restrict__ z, const float* __restrict__ emb) {
    extern __shared__ char smem[];
    const uint32_t sb = smem_u32(smem);
    const int tid   = threadIdx.x;
    const int w     = tid >> 5;
    const int lane  = tid & 31;
    const int mgrp  = w >> 1;          // 0..7: which 16 point-rows
    const int ngrp  = w & 1;           // 0..1: which 32-code half of the tile
    const int q     = lane >> 2;
    const int e     = lane & 3;
    const int n0    = blockIdx.x * BM;

    float*    en_s  = reinterpret_cast<float*>(smem + SM_EN);
    uint32_t* pbd_u = reinterpret_cast<uint32_t*>(smem + SM_PBD);
    int*      pcnt_s= reinterpret_cast<int*>(smem + SM_PCNT);
    float*    pcd_s = reinterpret_cast<float*>(smem + SM_PCD);
    int*      pck_s = reinterpret_cast<int*>(smem + SM_PCK);

    if (tid < BM) { pbd_u[tid] = 0xFFFFFFFFu; pcnt_s[tid] = 0; }

    // ---- Resident A fragments: 16 rows x full K=256, bf16 (64 regs) ----
    uint32_t Ah[64];
    {
        const __nv_bfloat16* zh1 = g_zhi + (size_t)(n0 + mgrp * 16 + q) * DIM;
        const __nv_bfloat16* zh2 = zh1 + 8 * DIM;
        #pragma unroll
        for (int ks = 0; ks < 16; ++ks) {
            int c0 = ks * 16 + 2 * e;
            Ah[ks*4+0] = *reinterpret_cast<const uint32_t*>(zh1 + c0);
            Ah[ks*4+1] = *reinterpret_cast<const uint32_t*>(zh2 + c0);
            Ah[ks*4+2] = *reinterpret_cast<const uint32_t*>(zh1 + c0 + 8);
            Ah[ks*4+3] = *reinterpret_cast<const uint32_t*>(zh2 + c0 + 8);
        }
    }

    // ---- B ldmatrix lane constants ----
    const int nl  = (lane & 7) | ((lane >> 4) << 3);
    const int h   = (lane >> 3) & 1;
    const int nl7 = nl & 7;

    // ---- cp.async prefetch: 512 thr x 4 x 16B = 32KB tile ----
    const int prow = tid >> 3;        // 0..63 (code row)
    const int pseg = tid & 7;         // 0..7 (16B seg)
    const uint32_t pswz = (uint32_t)((pseg ^ (prow & 7)) << 4);
    auto prefetch = [&](int t, int buf) {
        const __nv_bfloat16* gh = g_ehi + (size_t)(t * NT + prow) * DIM + pseg * 8;
        uint32_t dbase = sb + SM_EB + buf * 32768 + prow * 128 + pswz;
        #pragma unroll
        for (int dcp = 0; dcp < 4; ++dcp)
            cp_async16(dbase + dcp * 8192, gh + dcp * 64);
        CP_COMMIT();
    };
    auto load_en = [&](int t) {
        if (tid < NT) en_s[(t & 3) * NT + tid] = g_enorm[t * NT + tid];
    };

    const int p0 = mgrp * 16 + q;
    const int p1 = p0 + 8;

    // ---- per-tile consume (GEMM + distance filter) ----
    auto consume = [&](int t1) {
        float acc[16];
        #pragma unroll
        for (int i = 0; i < 16; ++i) acc[i] = 0.f;

        const uint32_t ebase = sb + SM_EB + (t1 & 3) * 32768 + (ngrp * 32 + nl) * 128;
        auto baddr = [&](int ks) -> uint32_t {
            return ebase + (ks >> 2) * 8192
                 + (uint32_t)(((((ks & 3) * 2) + h) ^ nl7) << 4);
        };

        uint32_t B[3][8];
        { uint32_t pa = baddr(0); ldsm_x4(B[0], pa); ldsm_x4(B[0] + 4, pa + 2048); }
        { uint32_t pa = baddr(1); ldsm_x4(B[1], pa); ldsm_x4(B[1] + 4, pa + 2048); }
        #pragma unroll
        for (int ks = 0; ks < 16; ++ks) {
            if (ks + 2 < 16) {
                uint32_t pa = baddr(ks + 2);
                ldsm_x4(B[(ks + 2) % 3], pa);
                ldsm_x4(B[(ks + 2) % 3] + 4, pa + 2048);
            }
            const uint32_t* Bk = B[ks % 3];
            uint32_t a0 = Ah[ks*4+0], a1 = Ah[ks*4+1],
                     a2 = Ah[ks*4+2], a3 = Ah[ks*4+3];
            mma_bf16(acc + 0,  a0, a1, a2, a3, Bk[0], Bk[1]);
            mma_bf16(acc + 4,  a0, a1, a2, a3, Bk[2], Bk[3]);
            mma_bf16(acc + 8,  a0, a1, a2, a3, Bk[4], Bk[5]);
            mma_bf16(acc + 12, a0, a1, a2, a3, Bk[6], Bk[7]);
        }

        // ---- convert acc -> approx distances (in place) ----
        const float* enb = en_s + (t1 & 3) * NT;
        #pragma unroll
        for (int jj = 0; jj < 2; ++jj) {
            #pragma unroll
            for (int cp = 0; cp < 2; ++cp) {
                int cl = ngrp * 32 + jj * 16 + cp * 8 + 2 * e;
                float2 en2 = *reinterpret_cast<const float2*>(enb + cl);
                float* a = acc + jj * 8 + cp * 4;
                a[0] = fmaf(-2.0f, a[0], en2.x);
                a[1] = fmaf(-2.0f, a[1], en2.y);
                a[2] = fmaf(-2.0f, a[2], en2.x);
                a[3] = fmaf(-2.0f, a[3], en2.y);
            }
        }
        float m0 = fminf(fminf(fminf(acc[0], acc[1]), fminf(acc[4], acc[5])),
                         fminf(fminf(acc[8], acc[9]), fminf(acc[12], acc[13])));
        float m1 = fminf(fminf(fminf(acc[2], acc[3]), fminf(acc[6], acc[7])),
                         fminf(fminf(acc[10], acc[11]), fminf(acc[14], acc[15])));
        uint32_t e0 = fenc(m0), e1 = fenc(m1);

        if (t1 == 0) {   // seed TRUE min of tile 0 before any recording
            atomicMin(&pbd_u[p0], e0);
            atomicMin(&pbd_u[p1], e1);
            __syncthreads();
        }

        float b0 = fdec(pbd_u[p0]) + MARGIN;   // true running min
        float b1 = fdec(pbd_u[p1]) + MARGIN;
        if (m0 < b0 || m1 < b1) {   // rare
            #pragma unroll
            for (int jj = 0; jj < 2; ++jj) {
                #pragma unroll
                for (int cp = 0; cp < 2; ++cp) {
                    int k0 = t1 * NT + ngrp * 32 + jj * 16 + cp * 8 + 2 * e;
                    const float* a = acc + jj * 8 + cp * 4;
                    if (a[0] < b0) {
                        int s = atomicAdd(&pcnt_s[p0], 1);
                        if (s < NSLOT) { pcd_s[p0*NSLOT+s] = a[0]; pck_s[p0*NSLOT+s] = k0; }
                    }
                    if (a[1] < b0) {
                        int s = atomicAdd(&pcnt_s[p0], 1);
                        if (s < NSLOT) { pcd_s[p0*NSLOT+s] = a[1]; pck_s[p0*NSLOT+s] = k0+1; }
                    }
                    if (a[2] < b1) {
                        int s = atomicAdd(&pcnt_s[p1], 1);
                        if (s < NSLOT) { pcd_s[p1*NSLOT+s] = a[2]; pck_s[p1*NSLOT+s] = k0; }
                    }
                    if (a[3] < b1) {
                        int s = atomicAdd(&pcnt_s[p1], 1);
                        if (s < NSLOT) { pcd_s[p1*NSLOT+s] = a[3]; pck_s[p1*NSLOT+s] = k0+1; }
                    }
                }
            }
        }
        if (t1 > 0) {
            if (e0 < pbd_u[p0]) atomicMin(&pbd_u[p0], e0);
            if (e1 < pbd_u[p1]) atomicMin(&pbd_u[p1], e1);
        }
    };

    // ---- 4-stage pipeline, barrier every 2 tiles ----
    prefetch(0, 0);
    prefetch(1, 1);
    load_en(0);
    load_en(1);

    #pragma unroll 1
    for (int t1 = 0; t1 < NTILES; t1 += 2) {
        CP_WAIT0();          // tiles t1, t1+1 data arrived (issued 2 tiles ago)
        __syncthreads();     // visibility + ALL warps done with tiles t1-2, t1-1
                             // => buffers (t1+2)%4, (t1+3)%4 are free to overwrite
        if (t1 + 2 < NTILES) {
            prefetch(t1 + 2, (t1 + 2) & 3);
            prefetch(t1 + 3, (t1 + 3) & 3);
            load_en(t1 + 2);
            load_en(t1 + 3);
        }
        consume(t1);
        consume(t1 + 1);
    }

    // ---- exact fp32 rescore of recorded candidates ----
    __syncthreads();
    if (tid < BM) {
        int p = tid;
        int n = n0 + p;
        int cnt = pcnt_s[p];
        int ov = (cnt > NSLOT);
        int lim = ov ? NSLOT : cnt;
        float bound = fdec(pbd_u[p]) + MARGIN;
        const float* zr = z + (size_t)(n >> 10) * (DIM * HWSZ) + (n & 1023);
        float bestd = CUDART_INF_F; int bestk = 0x7fffffff;
        #pragma unroll 1
        for (int j = 0; j < lim; ++j) {
            float dv = pcd_s[p * NSLOT + j];
            if (!(dv < bound)) continue;
            int kv = pck_s[p * NSLOT + j];
            const float* er = emb + (size_t)kv * DIM;
            float dot = 0.f;
            #pragma unroll 8
            for (int c = 0; c < DIM; ++c)
                dot = fmaf(zr[(size_t)c * HWSZ], er[c], dot);
            float dd = fmaf(-2.0f, dot, g_enorm[kv]);
            if (dd < bestd || (dd == bestd && kv < bestk)) { bestd = dd; bestk = kv; }
        }
        g_best_idx[n] = bestk;
        g_flag[n] = (unsigned)ov;
    }
}

// ---------------- Kernel 1b: exact full-scan fallback for overflowed points ----------------
__global__ void k_fb(const float* __restrict__ z, const float* __restrict__ emb) {
    int w = (blockIdx.x * blockDim.x + threadIdx.x) >> 5;
    int lane = threadIdx.x & 31;
    if (w >= NPTS) return;
    if (g_flag[w] == 0) return;
    const float* zr = z + (size_t)(w >> 10) * (DIM * HWSZ) + (w & 1023);
    float bd = CUDART_INF_F; int bk = 0x7fffffff;
    for (int k = lane; k < NCODE; k += 32) {
        const float* er = emb + (size_t)k * DIM;
        float dot = 0.f;
        #pragma unroll 8
        for (int c = 0; c < DIM; ++c)
            dot = fmaf(zr[(size_t)c * HWSZ], er[c], dot);
        float dd = fmaf(-2.0f, dot, g_enorm[k]);
        if (dd < bd || (dd == bd && k < bk)) { bd = dd; bk = k; }
    }
    #pragma unroll
    for (int off = 16; off > 0; off >>= 1) {
        float od = __shfl_xor_sync(0xffffffffu, bd, off);
        int   ok = __shfl_xor_sync(0xffffffffu, bk, off);
        if (od < bd || (od == bd && ok < bk)) { bd = od; bk = ok; }
    }
    if (lane == 0) g_best_idx[w] = bk;
}

// ---------------- Kernel 2: output writer ----------------
__global__ void k_write(const float* __restrict__ z, const float* __restrict__ emb,
                        float* __restrict__ out, int out_size) {
    int i = blockIdx.x * 256 + threadIdx.x;
    if (i >= out_size) return;
    if (i < ZQ_ELEMS) {
        int hw = i & 1023;
        int bc = i >> 10;
        int c  = bc & 255;
        int b  = bc >> 8;
        int n  = (b << 10) + hw;
        int k  = g_best_idx[n];
        float ev = emb[(size_t)k * DIM + c];
        float zv = z[i];
        out[i] = __fadd_rn(zv, __fsub_rn(ev, zv));
    } else {
        int j = i - ZQ_ELEMS;
        out[i] = (j < NPTS) ? (float)g_best_idx[j] : 0.0f;
    }
}

extern "C" void kernel_launch(void* const* d_in, const int* in_sizes, int n_in,
                              void* d_out, int out_size) {
    const float* z   = (const float*)d_in[0];
    const float* emb = (const float*)d_in[1];
    if (in_sizes[0] != ZQ_ELEMS) {
        const float* tmp = z; z = emb; emb = tmp;
    }
    float* out = (float*)d_out;

    cudaFuncSetAttribute(k_vq, cudaFuncAttributeMaxDynamicSharedMemorySize,
                         SMEM_TOTAL);

    k_enorm<<<NCODE / 8, 256>>>(emb);
    k_esplit<<<(NCODE * DIM) / 256, 256>>>(emb);
    k_zsplit<<<2048, 256>>>(z);
    k_vq<<<NPTS / BM, 512, SMEM_TOTAL>>>(z, emb);
    k_fb<<<NPTS / 8, 256>>>(z, emb);
    int wgrid = (out_size + 255) / 256;
    k_write<<<wgrid, 256>>>(z, emb, out, out_size);
}